// round 11
// baseline (speedup 1.0000x reference)
#include <cuda_runtime.h>
#include <cuda_fp16.h>
#include <cstdint>

typedef unsigned long long ULL;

#define NPAD 704
#define PART2 (2048L * NPAD)

// ---------------- scratch (static device arrays; no runtime alloc) ----------
__device__ __half g_Ah[2048L * 2048];          // fp16 hi of concat(x,feature) 8MB
__device__ __half g_Al[2048L * 2048];          // fp16 lo residual             8MB
__device__ __half g_Bh[2048L * NPAD];          // fp16 [Wep1^T | Wp1 fold | 0] 2.75MB
__device__ float g_part[3 * PART2];            // K-split partial outputs

// ---------------- packed f32x2 helpers --------------------------------------
__device__ __forceinline__ ULL pack2(float v) {
    ULL r; unsigned u = __float_as_uint(v);
    asm("mov.b64 %0, {%1, %1};" : "=l"(r) : "r"(u));
    return r;
}
__device__ __forceinline__ float2 unpack2(ULL p) {
    unsigned lo, hi;
    asm("mov.b64 {%0, %1}, %2;" : "=r"(lo), "=r"(hi) : "l"(p));
    return make_float2(__uint_as_float(lo), __uint_as_float(hi));
}
#define FFMA2(acc, a, b) asm("fma.rn.f32x2 %0, %1, %2, %0;" : "+l"(acc) : "l"(a), "l"(b))

// ---------------- mma.sync / ldmatrix / cp.async (sm_80 baseline) -----------
__device__ __forceinline__ uint32_t smem_u32(const void* p) {
    uint32_t a;
    asm("{ .reg .u64 t; cvta.to.shared.u64 t, %1; cvt.u32.u64 %0, t; }" : "=r"(a) : "l"(p));
    return a;
}
#define SW128(o) ((o) ^ (((o) >> 3) & 0x70))

#define LDSM_X4(r0, r1, r2, r3, addr) \
    asm volatile("ldmatrix.sync.aligned.m8n8.x4.shared.b16 {%0,%1,%2,%3}, [%4];" \
                 : "=r"(r0), "=r"(r1), "=r"(r2), "=r"(r3) : "r"(addr))
#define LDSM_X4T(r0, r1, r2, r3, addr) \
    asm volatile("ldmatrix.sync.aligned.m8n8.x4.trans.shared.b16 {%0,%1,%2,%3}, [%4];" \
                 : "=r"(r0), "=r"(r1), "=r"(r2), "=r"(r3) : "r"(addr))
#define MMA16816F16(d, a, b) \
    asm volatile("mma.sync.aligned.m16n8k16.row.col.f32.f16.f16.f32 " \
                 "{%0,%1,%2,%3}, {%4,%5,%6,%7}, {%8,%9}, {%0,%1,%2,%3};" \
                 : "+f"((d)[0]), "+f"((d)[1]), "+f"((d)[2]), "+f"((d)[3]) \
                 : "r"((a)[0]), "r"((a)[1]), "r"((a)[2]), "r"((a)[3]), \
                   "r"((b)[0]), "r"((b)[1]))
#define CP16(dst, src) \
    asm volatile("cp.async.cg.shared.global [%0], [%1], 16;" :: "r"(dst), "l"(src))
#define CP_COMMIT() asm volatile("cp.async.commit_group;" ::: "memory")
#define CP_WAIT1()  asm volatile("cp.async.wait_group 1;" ::: "memory")
#define CP_WAIT0()  asm volatile("cp.async.wait_group 0;" ::: "memory")

// ============================================================================
// Front kernel: dispatcher over [convert_A | convert_W] block ranges.
// ============================================================================
#define A_BLOCKS  2048
#define W_BLOCKS  704

__global__ __launch_bounds__(256) void k_front(
    const float* __restrict__ x, const float* __restrict__ f,
    const float* __restrict__ Wep1, const float* __restrict__ Wp1)
{
    const int t = threadIdx.x;
    const int bid = blockIdx.x;

    if (bid < A_BLOCKS) {
        // ---- convert A: fp16 hi + lo planes, source read once ----
        int idx = bid * 256 + t;                 // over 2048*256
        int m = idx >> 8;
        int k = (idx & 255) * 8;
        const float* src = (k < 1024) ? (x + (size_t)m * 1024 + k)
                                      : (f + (size_t)m * 1024 + (k - 1024));
        float4 f0 = *(const float4*)src;
        float4 f1 = *(const float4*)(src + 4);
        float vv[8] = {f0.x, f0.y, f0.z, f0.w, f1.x, f1.y, f1.z, f1.w};
        union { __half h[8]; uint4 u; } H, L;
#pragma unroll
        for (int e = 0; e < 8; ++e) {
            __half hb = __float2half(vv[e]);
            H.h[e] = hb;
            L.h[e] = __float2half(vv[e] - __half2float(hb));
        }
        *(uint4*)(g_Ah + (size_t)m * 2048 + k) = H.u;
        *(uint4*)(g_Al + (size_t)m * 2048 + k) = L.u;
    } else {
        // ---- convert W: [2048 k][704 n] fp16; 0-511 Wep1, 512-671 Wp1, pad 0 ----
        int idx = (bid - A_BLOCKS) * 256 + t;    // over 2048*88
        int k = idx / 88;
        int n = (idx - k * 88) * 8;
        float vv[8];
        if (n < 512) {
            float4 w0 = *(const float4*)&Wep1[(size_t)k * 512 + n];
            float4 w1 = *(const float4*)&Wep1[(size_t)k * 512 + n + 4];
            vv[0] = w0.x; vv[1] = w0.y; vv[2] = w0.z; vv[3] = w0.w;
            vv[4] = w1.x; vv[5] = w1.y; vv[6] = w1.z; vv[7] = w1.w;
        } else if (n < 672) {
#pragma unroll
            for (int e = 0; e < 8; ++e) {
                int u = n + e - 512, en = u / 5, r = u - en * 5;
                vv[e] = (k < 1024) ? Wp1[en * 5120 + k * 5 + r] : 0.f;
            }
        } else {
#pragma unroll
            for (int e = 0; e < 8; ++e) vv[e] = 0.f;
        }
        union { __half h[8]; uint4 u; } O;
#pragma unroll
        for (int e = 0; e < 8; ++e) O.h[e] = __float2half(vv[e]);
        *(uint4*)(g_Bh + (size_t)k * NPAD + n) = O.u;
    }
}

// ============================================================================
// HMMA GEMM (fp16, 2-product): D[2048,704] = (Ah+Al)[2048,2048] @ Bh[2048,704].
// BM=128 BN=64 BK=64, 256 thr (8 warps, 32x32 warp tiles), dual A-plane per
// chunk, 2-stage cp.async smem + REGISTER-double-buffered fragments: s+1's
// LDSMs are issued before s's MMAs so frag-load latency hides under MMA issue.
// ============================================================================
__device__ __forceinline__ void gemm_issue(int tid, int m0, int n0, int chunk,
                                           uint32_t sb, int stage) {
    const __half* Ah = g_Ah + (size_t)m0 * 2048 + chunk * 64;
    const __half* Al = g_Al + (size_t)m0 * 2048 + chunk * 64;
    const __half* Bb = g_Bh + (size_t)chunk * 64 * NPAD + n0;
    uint32_t sA = sb + stage * 49152;
    uint32_t sL = sA + 16384;
    uint32_t sB = sA + 32768;
#pragma unroll
    for (int i = 0; i < 4; ++i) {            // each plane: 128 rows x 128B
        int v = tid * 4 + i, m = v >> 3, q = v & 7;
        uint32_t so = SW128((uint32_t)(m * 128 + q * 16));
        CP16(sA + so, Ah + (size_t)m * 2048 + q * 8);
        CP16(sL + so, Al + (size_t)m * 2048 + q * 8);
    }
#pragma unroll
    for (int i = 0; i < 2; ++i) {            // B: 64 k-rows x 128B (64 n)
        int v = tid * 2 + i, kr = v >> 3, q = v & 7;
        uint32_t so = SW128((uint32_t)(kr * 128 + q * 16));
        CP16(sB + so, Bb + (size_t)kr * NPAD + q * 8);
    }
}

struct Frags { uint32_t aH[2][4], aL[2][4], bF[4][2]; };

__device__ __forceinline__ void load_frags(Frags& F, uint32_t sA, uint32_t sL,
                                           uint32_t sB, int s, int warp_m,
                                           int warp_n, int lane) {
    const int kh = s * 16 + (lane >> 4) * 8;
#pragma unroll
    for (int i = 0; i < 2; ++i) {
        int row = warp_m + i * 16 + ((lane >> 3) & 1) * 8 + (lane & 7);
        uint32_t so = SW128((uint32_t)(row * 128 + kh * 2));
        LDSM_X4(F.aH[i][0], F.aH[i][1], F.aH[i][2], F.aH[i][3], sA + so);
        LDSM_X4(F.aL[i][0], F.aL[i][1], F.aL[i][2], F.aL[i][3], sL + so);
    }
    const int kr = s * 16 + ((lane >> 3) & 1) * 8 + (lane & 7);
#pragma unroll
    for (int j2 = 0; j2 < 2; ++j2) {
        int ncol = warp_n + j2 * 16 + (lane >> 4) * 8;
        uint32_t bd = sB + SW128((uint32_t)(kr * 128 + ncol * 2));
        LDSM_X4T(F.bF[j2 * 2][0], F.bF[j2 * 2][1],
                 F.bF[j2 * 2 + 1][0], F.bF[j2 * 2 + 1][1], bd);
    }
}

__global__ __launch_bounds__(256, 2) void k_gemm() {
    extern __shared__ __align__(1024) char smem[];
    const uint32_t sb = smem_u32(smem);
    const int tid = threadIdx.x, lane = tid & 31, wid = tid >> 5;
    const int m0 = blockIdx.y * 128;
    const int n0 = blockIdx.x * 64;
    const int c0 = blockIdx.z * 11;
    const int nc = (blockIdx.z == 2) ? 10 : 11;
    const int warp_m = (wid & 3) * 32;
    const int warp_n = (wid >> 2) * 32;

    float acc[2][4][4] = {};
    Frags F[2];

    gemm_issue(tid, m0, n0, c0, sb, 0); CP_COMMIT();

    for (int ci = 0; ci < nc; ++ci) {
        if (ci + 1 < nc) {
            gemm_issue(tid, m0, n0, c0 + ci + 1, sb, (ci + 1) & 1);
            CP_COMMIT();
            CP_WAIT1();
        } else {
            CP_WAIT0();
        }
        __syncthreads();

        const uint32_t sA = sb + (ci & 1) * 49152;
        const uint32_t sL = sA + 16384;
        const uint32_t sB = sA + 32768;

        load_frags(F[0], sA, sL, sB, 0, warp_m, warp_n, lane);
#pragma unroll
        for (int s = 0; s < 4; ++s) {
            const int cb = s & 1, nb = cb ^ 1;
            if (s < 3)   // prefetch next s-step's frags before issuing MMAs
                load_frags(F[nb], sA, sL, sB, s + 1, warp_m, warp_n, lane);
#pragma unroll
            for (int i = 0; i < 2; ++i)
#pragma unroll
                for (int j = 0; j < 4; ++j) {
                    MMA16816F16(acc[i][j], F[cb].aH[i], F[cb].bF[j]);
                    MMA16816F16(acc[i][j], F[cb].aL[i], F[cb].bF[j]);
                }
        }
        __syncthreads();
    }

    float* dst = g_part + (size_t)blockIdx.z * PART2;
#pragma unroll
    for (int i = 0; i < 2; ++i)
#pragma unroll
        for (int j = 0; j < 4; ++j) {
            int r = m0 + warp_m + i * 16 + (lane >> 2);
            int cC = n0 + warp_n + j * 8 + (lane & 3) * 2;
            *(float2*)&dst[(size_t)r * NPAD + cC] = make_float2(acc[i][j][0], acc[i][j][1]);
            *(float2*)&dst[(size_t)(r + 8) * NPAD + cC] = make_float2(acc[i][j][2], acc[i][j][3]);
        }
}

// ============================================================================
// Fused tail: 2 b-rows (16 (b,n) rows) per block, 512 threads, dyn smem 68KB.
// ============================================================================
__global__ __launch_bounds__(512) void k_tail(
    const float* __restrict__ z, const float* __restrict__ Wep1,
    const float* __restrict__ W2, const float* __restrict__ bep1,
    const float* __restrict__ bep2,
    const float* __restrict__ bp1, const float* __restrict__ Wp2,
    const float* __restrict__ bp2, const float* __restrict__ Wp3,
    const float* __restrict__ bp3, float* __restrict__ out)
{
    extern __shared__ float dsm[];
    float* zsT = dsm;                    // [32][16]
    float* zs  = dsm + 512;              // [16][32]
    float* ps  = dsm + 1024;             // [64]
    float* hs  = dsm + 1088;             // [16][512]
    float* wzs = dsm + 1088 + 8192;      // [16][512]

    const int t = threadIdx.x;
    const int r0 = blockIdx.x * 16;
    const int b0 = blockIdx.x * 2;

    // Wep2 row j=t: issue LDGs immediately (64KB, L2-resident after wave 1)
    float w[32];
#pragma unroll
    for (int q8 = 0; q8 < 8; ++q8)
        *(float4*)&w[q8 * 4] = *(const float4*)&W2[t * 32 + q8 * 4];

    {
        const int row = t >> 5, o = t & 31;
        float v = z[(size_t)(r0 + row) * 32 + o];
        zs[row * 32 + o] = v;
        zsT[o * 16 + row] = v;
    }

    // prior ensemble inputs: issue LDGs early (consumed after phase A)
    float pr[15];
    if (t < 64) {
        const int bb = b0 + (t >> 5), e = t & 31;
        const size_t off = (size_t)bb * NPAD + 512 + e * 5;
#pragma unroll
        for (int s = 0; s < 3; ++s)
#pragma unroll
            for (int k = 0; k < 5; ++k)
                pr[s * 5 + k] = g_part[s * PART2 + off + k];
    }
    __syncthreads();

    // ---- wz: wzs[row][t] = sum_o Wep2[t][o] * z[row][o], packed row pairs ----
    {
        ULL wacc[8] = {0ULL, 0ULL, 0ULL, 0ULL, 0ULL, 0ULL, 0ULL, 0ULL};
#pragma unroll 8
        for (int o = 0; o < 32; ++o) {
            ULL wo = pack2(w[o]);
#pragma unroll
            for (int u = 0; u < 8; ++u)
                FFMA2(wacc[u], *(const ULL*)&zsT[o * 16 + 2 * u], wo);
        }
#pragma unroll
        for (int u = 0; u < 8; ++u) {
            float2 v = unpack2(wacc[u]);
            wzs[(2 * u) * 512 + t]     = v.x;
            wzs[(2 * u + 1) * 512 + t] = v.y;
        }
    }

    // ---- phase A: j = t ----
    {
        const int j = t;
        const float* W1z = Wep1 + 2048 * 512;
        const float be = bep1[j];
        float base0 = be, base1 = be;
#pragma unroll
        for (int s = 0; s < 3; ++s) {
            base0 += g_part[s * PART2 + (size_t)b0 * NPAD + j];
            base1 += g_part[s * PART2 + (size_t)(b0 + 1) * NPAD + j];
        }
        ULL acc[8];
#pragma unroll
        for (int u = 0; u < 8; ++u) acc[u] = pack2(u < 4 ? base0 : base1);
#pragma unroll 4
        for (int q = 0; q < 32; ++q) {
            ULL ww = pack2(W1z[q * 512 + j]);
#pragma unroll
            for (int u = 0; u < 8; ++u)
                FFMA2(acc[u], *(const ULL*)&zsT[q * 16 + 2 * u], ww);
        }
#pragma unroll
        for (int u = 0; u < 8; ++u) {
            float2 v = unpack2(acc[u]);
            hs[(2 * u) * 512 + j]     = fmaxf(v.x, 0.f);
            hs[(2 * u + 1) * 512 + j] = fmaxf(v.y, 0.f);
        }
    }

    // prior ensemble layers 2-3
    if (t < 64) {
        const int e = t & 31;
        float s1[5];
#pragma unroll
        for (int k = 0; k < 5; ++k)
            s1[k] = fmaxf(pr[k] + pr[5 + k] + pr[10 + k] + bp1[e * 5 + k], 0.f);
        float p = bp3[e];
#pragma unroll
        for (int g = 0; g < 5; ++g) {
            float s = bp2[e * 5 + g];
#pragma unroll
            for (int k = 0; k < 5; ++k) s += s1[k] * Wp2[e * 25 + k * 5 + g];
            p += fmaxf(s, 0.f) * Wp3[e * 5 + g];
        }
        ps[t] = p;
    }
    __syncthreads();

    // ---- phase B: warp w = row, lane l; all operands in smem ----
    {
        const int w2 = t >> 5, l = t & 31;
        const float4* h4 = (const float4*)&hs[w2 * 512];
        const float4* w4 = (const float4*)&wzs[w2 * 512];
        float acc = 0.f;
#pragma unroll
        for (int it = 0; it < 4; ++it) {
            float4 hv = h4[it * 32 + l];
            float4 wv = w4[it * 32 + l];
            acc += hv.x * wv.x + hv.y * wv.y + hv.z * wv.z + hv.w * wv.w;
        }
        acc += (bep2[l] + ps[(w2 >> 3) * 32 + l]) * zs[w2 * 32 + l];
#pragma unroll
        for (int off = 16; off > 0; off >>= 1)
            acc += __shfl_xor_sync(0xffffffffu, acc, off);
        if (l == 0) out[r0 + w2] = acc;
    }
}

// ============================================================================
extern "C" void kernel_launch(void* const* d_in, const int* in_sizes, int n_in,
                              void* d_out, int out_size)
{
    const float* x    = (const float*)d_in[0];
    const float* feat = (const float*)d_in[1];
    const float* z    = (const float*)d_in[2];
    const float* Wep1 = (const float*)d_in[3];
    const float* bep1 = (const float*)d_in[4];
    const float* Wep2 = (const float*)d_in[5];
    const float* bep2 = (const float*)d_in[6];
    const float* Wp1  = (const float*)d_in[7];
    const float* bp1  = (const float*)d_in[8];
    const float* Wp2  = (const float*)d_in[9];
    const float* bp2  = (const float*)d_in[10];
    const float* Wp3  = (const float*)d_in[11];
    const float* bp3  = (const float*)d_in[12];
    float* out = (float*)d_out;

    static int smem_set = 0;
    if (!smem_set) {
        cudaFuncSetAttribute(k_gemm, cudaFuncAttributeMaxDynamicSharedMemorySize, 98304);
        cudaFuncSetAttribute(k_tail, cudaFuncAttributeMaxDynamicSharedMemorySize, 70912);
        smem_set = 1;
    }

    k_front<<<A_BLOCKS + W_BLOCKS, 256>>>(x, feat, Wep1, Wp1);
    k_gemm<<<dim3(11, 16, 3), 256, 98304>>>();
    k_tail<<<1024, 512, 69888>>>(z, Wep1, Wep2, bep1, bep2,
                                 bp1, Wp2, bp2, Wp3, bp3, out);
}

// round 12
// speedup vs baseline: 1.5108x; 1.5108x over previous
#include <cuda_runtime.h>
#include <cuda_fp16.h>
#include <cstdint>

typedef unsigned long long ULL;

#define NPAD 704
#define PART2 (2048L * NPAD)

// ---------------- scratch (static device arrays; no runtime alloc) ----------
__device__ __half g_Ah[2048L * 2048];          // fp16 of concat(x,feature)  8MB
__device__ __half g_Bh[2048L * NPAD];          // fp16 [Wep1^T | Wp1 fold | 0]
__device__ float g_part[3 * PART2];            // K-split partial outputs
__device__ float g_W2T[32 * 512];              // Wep2 transposed [o][j]

// ---------------- packed f32x2 helpers --------------------------------------
__device__ __forceinline__ ULL pack2(float v) {
    ULL r; unsigned u = __float_as_uint(v);
    asm("mov.b64 %0, {%1, %1};" : "=l"(r) : "r"(u));
    return r;
}
__device__ __forceinline__ float2 unpack2(ULL p) {
    unsigned lo, hi;
    asm("mov.b64 {%0, %1}, %2;" : "=r"(lo), "=r"(hi) : "l"(p));
    return make_float2(__uint_as_float(lo), __uint_as_float(hi));
}
#define FFMA2(acc, a, b) asm("fma.rn.f32x2 %0, %1, %2, %0;" : "+l"(acc) : "l"(a), "l"(b))

// ---------------- mma.sync / ldmatrix / cp.async (sm_80 baseline) -----------
__device__ __forceinline__ uint32_t smem_u32(const void* p) {
    uint32_t a;
    asm("{ .reg .u64 t; cvta.to.shared.u64 t, %1; cvt.u32.u64 %0, t; }" : "=r"(a) : "l"(p));
    return a;
}
#define SW128(o) ((o) ^ (((o) >> 3) & 0x70))

#define LDSM_X4(r0, r1, r2, r3, addr) \
    asm volatile("ldmatrix.sync.aligned.m8n8.x4.shared.b16 {%0,%1,%2,%3}, [%4];" \
                 : "=r"(r0), "=r"(r1), "=r"(r2), "=r"(r3) : "r"(addr))
#define LDSM_X4T(r0, r1, r2, r3, addr) \
    asm volatile("ldmatrix.sync.aligned.m8n8.x4.trans.shared.b16 {%0,%1,%2,%3}, [%4];" \
                 : "=r"(r0), "=r"(r1), "=r"(r2), "=r"(r3) : "r"(addr))
#define MMA16816F16(d, a, b) \
    asm volatile("mma.sync.aligned.m16n8k16.row.col.f32.f16.f16.f32 " \
                 "{%0,%1,%2,%3}, {%4,%5,%6,%7}, {%8,%9}, {%0,%1,%2,%3};" \
                 : "+f"((d)[0]), "+f"((d)[1]), "+f"((d)[2]), "+f"((d)[3]) \
                 : "r"((a)[0]), "r"((a)[1]), "r"((a)[2]), "r"((a)[3]), \
                   "r"((b)[0]), "r"((b)[1]))
#define CP16(dst, src) \
    asm volatile("cp.async.cg.shared.global [%0], [%1], 16;" :: "r"(dst), "l"(src))
#define CP_COMMIT() asm volatile("cp.async.commit_group;" ::: "memory")
#define CP_WAIT1()  asm volatile("cp.async.wait_group 1;" ::: "memory")
#define CP_WAIT0()  asm volatile("cp.async.wait_group 0;" ::: "memory")

// ============================================================================
// Front kernel: dispatcher over [convert_A | convert_W | W2 transpose].
// ============================================================================
#define A_BLOCKS  2048
#define W_BLOCKS  704
#define T_BLOCKS  16

__global__ __launch_bounds__(256) void k_front(
    const float* __restrict__ x, const float* __restrict__ f,
    const float* __restrict__ Wep1, const float* __restrict__ Wp1,
    const float* __restrict__ W2)
{
    const int t = threadIdx.x;
    const int bid = blockIdx.x;

    if (bid < A_BLOCKS) {
        // ---- convert A: single fp16 plane, source read once ----
        int idx = bid * 256 + t;                 // over 2048*256
        int m = idx >> 8;
        int k = (idx & 255) * 8;
        const float* src = (k < 1024) ? (x + (size_t)m * 1024 + k)
                                      : (f + (size_t)m * 1024 + (k - 1024));
        float4 f0 = *(const float4*)src;
        float4 f1 = *(const float4*)(src + 4);
        float vv[8] = {f0.x, f0.y, f0.z, f0.w, f1.x, f1.y, f1.z, f1.w};
        union { __half h[8]; uint4 u; } H;
#pragma unroll
        for (int e = 0; e < 8; ++e) H.h[e] = __float2half(vv[e]);
        *(uint4*)(g_Ah + (size_t)m * 2048 + k) = H.u;
    } else if (bid < A_BLOCKS + W_BLOCKS) {
        // ---- convert W: [2048 k][704 n] fp16; 0-511 Wep1, 512-671 Wp1, pad 0 ----
        int idx = (bid - A_BLOCKS) * 256 + t;    // over 2048*88
        int k = idx / 88;
        int n = (idx - k * 88) * 8;
        float vv[8];
        if (n < 512) {
            float4 w0 = *(const float4*)&Wep1[(size_t)k * 512 + n];
            float4 w1 = *(const float4*)&Wep1[(size_t)k * 512 + n + 4];
            vv[0] = w0.x; vv[1] = w0.y; vv[2] = w0.z; vv[3] = w0.w;
            vv[4] = w1.x; vv[5] = w1.y; vv[6] = w1.z; vv[7] = w1.w;
        } else if (n < 672) {
#pragma unroll
            for (int e = 0; e < 8; ++e) {
                int u = n + e - 512, en = u / 5, r = u - en * 5;
                vv[e] = (k < 1024) ? Wp1[en * 5120 + k * 5 + r] : 0.f;
            }
        } else {
#pragma unroll
            for (int e = 0; e < 8; ++e) vv[e] = 0.f;
        }
        union { __half h[8]; uint4 u; } O;
#pragma unroll
        for (int e = 0; e < 8; ++e) O.h[e] = __float2half(vv[e]);
        *(uint4*)(g_Bh + (size_t)k * NPAD + n) = O.u;
    } else {
        // ---- W2T[o][j] = Wep2[j][o] (64KB, read once) ----
        int idx = (bid - A_BLOCKS - W_BLOCKS) * 1024 + t * 4;   // over 16384
        int o = idx >> 9;
#pragma unroll
        for (int e = 0; e < 4; ++e) {
            int j = (idx + e) & 511;
            g_W2T[o * 512 + j] = W2[j * 32 + o];
        }
    }
}

// ============================================================================
// HMMA GEMM (fp16 single-product): D[2048,704] = A[2048,2048] @ B[2048,704].
// BM=128 BN=64 BK=64, 256 thr (8 warps, 32x32 warp tiles), 2-stage cp.async
// (24KB/stage), K-split 3. Runs at the fallback-HMMA rate (~512 MAC/cyc/SM).
// ============================================================================
__device__ __forceinline__ void gemm_issue(int tid, int m0, int n0, int chunk,
                                           uint32_t sb, int stage) {
    const __half* Ah = g_Ah + (size_t)m0 * 2048 + chunk * 64;
    const __half* Bb = g_Bh + (size_t)chunk * 64 * NPAD + n0;
    uint32_t sA = sb + stage * 24576;
    uint32_t sB = sA + 16384;
#pragma unroll
    for (int i = 0; i < 4; ++i) {            // A: 128 rows x 128B
        int v = tid * 4 + i, m = v >> 3, q = v & 7;
        uint32_t so = SW128((uint32_t)(m * 128 + q * 16));
        CP16(sA + so, Ah + (size_t)m * 2048 + q * 8);
    }
#pragma unroll
    for (int i = 0; i < 2; ++i) {            // B: 64 k-rows x 128B (64 n)
        int v = tid * 2 + i, kr = v >> 3, q = v & 7;
        uint32_t so = SW128((uint32_t)(kr * 128 + q * 16));
        CP16(sB + so, Bb + (size_t)kr * NPAD + q * 8);
    }
}

__global__ __launch_bounds__(256, 2) void k_gemm() {
    extern __shared__ __align__(1024) char smem[];
    const uint32_t sb = smem_u32(smem);
    const int tid = threadIdx.x, lane = tid & 31, wid = tid >> 5;
    const int m0 = blockIdx.y * 128;
    const int n0 = blockIdx.x * 64;
    const int c0 = blockIdx.z * 11;
    const int nc = (blockIdx.z == 2) ? 10 : 11;
    const int warp_m = (wid & 3) * 32;
    const int warp_n = (wid >> 2) * 32;

    float acc[2][4][4] = {};

    gemm_issue(tid, m0, n0, c0, sb, 0); CP_COMMIT();

    for (int ci = 0; ci < nc; ++ci) {
        if (ci + 1 < nc) {
            gemm_issue(tid, m0, n0, c0 + ci + 1, sb, (ci + 1) & 1);
            CP_COMMIT();
            CP_WAIT1();
        } else {
            CP_WAIT0();
        }
        __syncthreads();

        const uint32_t sA = sb + (ci & 1) * 24576;
        const uint32_t sB = sA + 16384;
#pragma unroll
        for (int s = 0; s < 4; ++s) {
            uint32_t aH[2][4], bF[4][2];
            const int kh = s * 16 + (lane >> 4) * 8;
#pragma unroll
            for (int i = 0; i < 2; ++i) {
                int row = warp_m + i * 16 + ((lane >> 3) & 1) * 8 + (lane & 7);
                uint32_t so = SW128((uint32_t)(row * 128 + kh * 2));
                LDSM_X4(aH[i][0], aH[i][1], aH[i][2], aH[i][3], sA + so);
            }
            const int kr = s * 16 + ((lane >> 3) & 1) * 8 + (lane & 7);
#pragma unroll
            for (int j2 = 0; j2 < 2; ++j2) {
                int ncol = warp_n + j2 * 16 + (lane >> 4) * 8;
                uint32_t bd = sB + SW128((uint32_t)(kr * 128 + ncol * 2));
                LDSM_X4T(bF[j2 * 2][0], bF[j2 * 2][1],
                         bF[j2 * 2 + 1][0], bF[j2 * 2 + 1][1], bd);
            }
#pragma unroll
            for (int i = 0; i < 2; ++i)
#pragma unroll
                for (int j = 0; j < 4; ++j)
                    MMA16816F16(acc[i][j], aH[i], bF[j]);
        }
        __syncthreads();
    }

    float* dst = g_part + (size_t)blockIdx.z * PART2;
#pragma unroll
    for (int i = 0; i < 2; ++i)
#pragma unroll
        for (int j = 0; j < 4; ++j) {
            int r = m0 + warp_m + i * 16 + (lane >> 2);
            int cC = n0 + warp_n + j * 8 + (lane & 3) * 2;
            *(float2*)&dst[(size_t)r * NPAD + cC] = make_float2(acc[i][j][0], acc[i][j][1]);
            *(float2*)&dst[(size_t)(r + 8) * NPAD + cC] = make_float2(acc[i][j][2], acc[i][j][3]);
        }
}

// ============================================================================
// Fused tail: 2 b-rows (16 (b,n) rows) per block, 512 threads, 2 blocks/SM
// (launch_bounds-forced <=64 regs; no reg-array caches).
//  wz: wzs[row][t] = sum_o W2T[o][t] * z[row][o]  (coalesced LDG.32 per o)
//  A:  h[row][j] = relu(base[b,j]+bep1[j] + sum_q z[row][q]*Wep1[2048+q, j])
//  prior: 64 threads, ensemble layers 2-3 (direct LDGs, L2-resident)
//  B:  out[row] = hs[row].wzs[row] + sum_o (bep2[o]+p[b,o])*z[row][o]
// ============================================================================
__global__ __launch_bounds__(512, 2) void k_tail(
    const float* __restrict__ z, const float* __restrict__ Wep1,
    const float* __restrict__ bep1, const float* __restrict__ bep2,
    const float* __restrict__ bp1, const float* __restrict__ Wp2,
    const float* __restrict__ bp2, const float* __restrict__ Wp3,
    const float* __restrict__ bp3, float* __restrict__ out)
{
    extern __shared__ float dsm[];
    float* zsT = dsm;                    // [32][16]
    float* zs  = dsm + 512;              // [16][32]
    float* ps  = dsm + 1024;             // [64]
    float* hs  = dsm + 1088;             // [16][512]
    float* wzs = dsm + 1088 + 8192;      // [16][512]

    const int t = threadIdx.x;
    const int r0 = blockIdx.x * 16;
    const int b0 = blockIdx.x * 2;

    {
        const int row = t >> 5, o = t & 31;
        float v = z[(size_t)(r0 + row) * 32 + o];
        zs[row * 32 + o] = v;
        zsT[o * 16 + row] = v;
    }
    __syncthreads();

    // ---- wz: wzs[row][t] = sum_o W2T[o][t] * z[row][o] ----
    {
        ULL wacc[8] = {0ULL, 0ULL, 0ULL, 0ULL, 0ULL, 0ULL, 0ULL, 0ULL};
#pragma unroll 4
        for (int o = 0; o < 32; ++o) {
            ULL wo = pack2(g_W2T[o * 512 + t]);
#pragma unroll
            for (int u = 0; u < 8; ++u)
                FFMA2(wacc[u], *(const ULL*)&zsT[o * 16 + 2 * u], wo);
        }
#pragma unroll
        for (int u = 0; u < 8; ++u) {
            float2 v = unpack2(wacc[u]);
            wzs[(2 * u) * 512 + t]     = v.x;
            wzs[(2 * u + 1) * 512 + t] = v.y;
        }
    }

    // ---- phase A: j = t ----
    {
        const int j = t;
        const float* W1z = Wep1 + 2048 * 512;
        const float be = bep1[j];
        float base0 = be, base1 = be;
#pragma unroll
        for (int s = 0; s < 3; ++s) {
            base0 += g_part[s * PART2 + (size_t)b0 * NPAD + j];
            base1 += g_part[s * PART2 + (size_t)(b0 + 1) * NPAD + j];
        }
        ULL acc[8];
#pragma unroll
        for (int u = 0; u < 8; ++u) acc[u] = pack2(u < 4 ? base0 : base1);
#pragma unroll 4
        for (int q = 0; q < 32; ++q) {
            ULL ww = pack2(W1z[q * 512 + j]);
#pragma unroll
            for (int u = 0; u < 8; ++u)
                FFMA2(acc[u], *(const ULL*)&zsT[q * 16 + 2 * u], ww);
        }
#pragma unroll
        for (int u = 0; u < 8; ++u) {
            float2 v = unpack2(acc[u]);
            hs[(2 * u) * 512 + t]     = fmaxf(v.x, 0.f);
            hs[(2 * u + 1) * 512 + t] = fmaxf(v.y, 0.f);
        }
    }

    // prior ensemble layers 2-3 (direct LDGs; g_part rows are L2-warm)
    if (t < 64) {
        const int bb = b0 + (t >> 5), e = t & 31;
        const size_t off = (size_t)bb * NPAD + 512 + e * 5;
        float s1[5];
#pragma unroll
        for (int k = 0; k < 5; ++k)
            s1[k] = fmaxf(g_part[off + k] + g_part[PART2 + off + k]
                          + g_part[2 * PART2 + off + k] + bp1[e * 5 + k], 0.f);
        float p = bp3[e];
#pragma unroll
        for (int g = 0; g < 5; ++g) {
            float s = bp2[e * 5 + g];
#pragma unroll
            for (int k = 0; k < 5; ++k) s += s1[k] * Wp2[e * 25 + k * 5 + g];
            p += fmaxf(s, 0.f) * Wp3[e * 5 + g];
        }
        ps[t] = p;
    }
    __syncthreads();

    // ---- phase B: warp w2 = row, lane l; all operands in smem ----
    {
        const int w2 = t >> 5, l = t & 31;
        const float4* h4 = (const float4*)&hs[w2 * 512];
        const float4* w4 = (const float4*)&wzs[w2 * 512];
        float acc = 0.f;
#pragma unroll
        for (int it = 0; it < 4; ++it) {
            float4 hv = h4[it * 32 + l];
            float4 wv = w4[it * 32 + l];
            acc += hv.x * wv.x + hv.y * wv.y + hv.z * wv.z + hv.w * wv.w;
        }
        acc += (bep2[l] + ps[(w2 >> 3) * 32 + l]) * zs[w2 * 32 + l];
#pragma unroll
        for (int off = 16; off > 0; off >>= 1)
            acc += __shfl_xor_sync(0xffffffffu, acc, off);
        if (l == 0) out[r0 + w2] = acc;
    }
}

// ============================================================================
extern "C" void kernel_launch(void* const* d_in, const int* in_sizes, int n_in,
                              void* d_out, int out_size)
{
    const float* x    = (const float*)d_in[0];
    const float* feat = (const float*)d_in[1];
    const float* z    = (const float*)d_in[2];
    const float* Wep1 = (const float*)d_in[3];
    const float* bep1 = (const float*)d_in[4];
    const float* Wep2 = (const float*)d_in[5];
    const float* bep2 = (const float*)d_in[6];
    const float* Wp1  = (const float*)d_in[7];
    const float* bp1  = (const float*)d_in[8];
    const float* Wp2  = (const float*)d_in[9];
    const float* bp2  = (const float*)d_in[10];
    const float* Wp3  = (const float*)d_in[11];
    const float* bp3  = (const float*)d_in[12];
    float* out = (float*)d_out;

    static int smem_set = 0;
    if (!smem_set) {
        cudaFuncSetAttribute(k_gemm, cudaFuncAttributeMaxDynamicSharedMemorySize, 49152);
        cudaFuncSetAttribute(k_tail, cudaFuncAttributeMaxDynamicSharedMemorySize, 70912);
        smem_set = 1;
    }

    k_front<<<A_BLOCKS + W_BLOCKS + T_BLOCKS, 256>>>(x, feat, Wep1, Wp1, Wep2);
    k_gemm<<<dim3(11, 16, 3), 256, 49152>>>();
    k_tail<<<1024, 512, 69888>>>(z, Wep1, bep1, bep2,
                                 bp1, Wp2, bp2, Wp3, bp3, out);
}

// round 14
// speedup vs baseline: 1.7772x; 1.1763x over previous
#include <cuda_runtime.h>
#include <cuda_fp16.h>
#include <cstdint>

typedef unsigned long long ULL;

#define NPAD 704
#define PART2 (2048L * NPAD)

// ---------------- scratch (static device arrays; no runtime alloc) ----------
__device__ __half g_Ah[2048L * 2048];          // fp16 of concat(x,feature)  8MB
__device__ __half g_Bh[2048L * NPAD];          // fp16 [Wep1^T | Wp1 fold | 0]
__device__ float g_part[3 * PART2];            // K-split partial outputs
__device__ __half g_W1zh[32 * 512];            // fp16 Wep1 rows 2048.. (z block)
__device__ __half g_W2h[512 * 32];             // fp16 Wep2

// ---------------- helpers ----------------------------------------------------
__device__ __forceinline__ uint32_t smem_u32(const void* p) {
    uint32_t a;
    asm("{ .reg .u64 t; cvta.to.shared.u64 t, %1; cvt.u32.u64 %0, t; }" : "=r"(a) : "l"(p));
    return a;
}
__device__ __forceinline__ uint32_t packh2(__half a, __half b) {
    __half2 p = __halves2half2(a, b);
    return *(uint32_t*)&p;
}
#define SW128(o) ((o) ^ (((o) >> 3) & 0x70))

#define LDSM_X4(r0, r1, r2, r3, addr) \
    asm volatile("ldmatrix.sync.aligned.m8n8.x4.shared.b16 {%0,%1,%2,%3}, [%4];" \
                 : "=r"(r0), "=r"(r1), "=r"(r2), "=r"(r3) : "r"(addr))
#define LDSM_X4T(r0, r1, r2, r3, addr) \
    asm volatile("ldmatrix.sync.aligned.m8n8.x4.trans.shared.b16 {%0,%1,%2,%3}, [%4];" \
                 : "=r"(r0), "=r"(r1), "=r"(r2), "=r"(r3) : "r"(addr))
#define MMA16816F16(d, a, b) \
    asm volatile("mma.sync.aligned.m16n8k16.row.col.f32.f16.f16.f32 " \
                 "{%0,%1,%2,%3}, {%4,%5,%6,%7}, {%8,%9}, {%0,%1,%2,%3};" \
                 : "+f"((d)[0]), "+f"((d)[1]), "+f"((d)[2]), "+f"((d)[3]) \
                 : "r"((a)[0]), "r"((a)[1]), "r"((a)[2]), "r"((a)[3]), \
                   "r"((b)[0]), "r"((b)[1]))
#define CP16(dst, src) \
    asm volatile("cp.async.cg.shared.global [%0], [%1], 16;" :: "r"(dst), "l"(src))
#define CP_COMMIT() asm volatile("cp.async.commit_group;" ::: "memory")
#define CP_WAIT1()  asm volatile("cp.async.wait_group 1;" ::: "memory")
#define CP_WAIT0()  asm volatile("cp.async.wait_group 0;" ::: "memory")

// ============================================================================
// Front kernel: dispatcher [convert_A | convert_W | small-weight fp16 converts]
// ============================================================================
#define A_BLOCKS  2048
#define W_BLOCKS  704
#define FH_BLOCKS 16

__global__ __launch_bounds__(256) void k_front(
    const float* __restrict__ x, const float* __restrict__ f,
    const float* __restrict__ Wep1, const float* __restrict__ Wp1,
    const float* __restrict__ W2)
{
    const int t = threadIdx.x;
    const int bid = blockIdx.x;

    if (bid < A_BLOCKS) {
        // ---- convert A: single fp16 plane, source read once ----
        int idx = bid * 256 + t;                 // over 2048*256
        int m = idx >> 8;
        int k = (idx & 255) * 8;
        const float* src = (k < 1024) ? (x + (size_t)m * 1024 + k)
                                      : (f + (size_t)m * 1024 + (k - 1024));
        float4 f0 = *(const float4*)src;
        float4 f1 = *(const float4*)(src + 4);
        float vv[8] = {f0.x, f0.y, f0.z, f0.w, f1.x, f1.y, f1.z, f1.w};
        union { __half h[8]; uint4 u; } H;
#pragma unroll
        for (int e = 0; e < 8; ++e) H.h[e] = __float2half(vv[e]);
        *(uint4*)(g_Ah + (size_t)m * 2048 + k) = H.u;
    } else if (bid < A_BLOCKS + W_BLOCKS) {
        // ---- convert W: [2048 k][704 n] fp16; 0-511 Wep1, 512-671 Wp1, pad 0 ----
        int idx = (bid - A_BLOCKS) * 256 + t;    // over 2048*88
        int k = idx / 88;
        int n = (idx - k * 88) * 8;
        float vv[8];
        if (n < 512) {
            float4 w0 = *(const float4*)&Wep1[(size_t)k * 512 + n];
            float4 w1 = *(const float4*)&Wep1[(size_t)k * 512 + n + 4];
            vv[0] = w0.x; vv[1] = w0.y; vv[2] = w0.z; vv[3] = w0.w;
            vv[4] = w1.x; vv[5] = w1.y; vv[6] = w1.z; vv[7] = w1.w;
        } else if (n < 672) {
#pragma unroll
            for (int e = 0; e < 8; ++e) {
                int u = n + e - 512, en = u / 5, r = u - en * 5;
                vv[e] = (k < 1024) ? Wp1[en * 5120 + k * 5 + r] : 0.f;
            }
        } else {
#pragma unroll
            for (int e = 0; e < 8; ++e) vv[e] = 0.f;
        }
        union { __half h[8]; uint4 u; } O;
#pragma unroll
        for (int e = 0; e < 8; ++e) O.h[e] = __float2half(vv[e]);
        *(uint4*)(g_Bh + (size_t)k * NPAD + n) = O.u;
    } else {
        // ---- fp16 converts of W1z (Wep1 rows 2048+) and Wep2 (32768 elems) ----
        int idx = (bid - A_BLOCKS - W_BLOCKS) * 2048 + t * 8;   // over 32768
        const float* src = (idx < 16384) ? (Wep1 + 2048 * 512 + idx)
                                         : (W2 + idx - 16384);
        __half* dst = (idx < 16384) ? (g_W1zh + idx) : (g_W2h + idx - 16384);
        float4 f0 = *(const float4*)src;
        float4 f1 = *(const float4*)(src + 4);
        float vv[8] = {f0.x, f0.y, f0.z, f0.w, f1.x, f1.y, f1.z, f1.w};
        union { __half h[8]; uint4 u; } O;
#pragma unroll
        for (int e = 0; e < 8; ++e) O.h[e] = __float2half(vv[e]);
        *(uint4*)dst = O.u;
    }
}

// ============================================================================
// HMMA GEMM (fp16 single-product): D[2048,704] = A[2048,2048] @ B[2048,704].
// BM=128 BN=64 BK=64, 256 thr (8 warps, 32x32 warp tiles), 2-stage cp.async.
// ============================================================================
__device__ __forceinline__ void gemm_issue(int tid, int m0, int n0, int chunk,
                                           uint32_t sb, int stage) {
    const __half* Ah = g_Ah + (size_t)m0 * 2048 + chunk * 64;
    const __half* Bb = g_Bh + (size_t)chunk * 64 * NPAD + n0;
    uint32_t sA = sb + stage * 24576;
    uint32_t sB = sA + 16384;
#pragma unroll
    for (int i = 0; i < 4; ++i) {
        int v = tid * 4 + i, m = v >> 3, q = v & 7;
        uint32_t so = SW128((uint32_t)(m * 128 + q * 16));
        CP16(sA + so, Ah + (size_t)m * 2048 + q * 8);
    }
#pragma unroll
    for (int i = 0; i < 2; ++i) {
        int v = tid * 2 + i, kr = v >> 3, q = v & 7;
        uint32_t so = SW128((uint32_t)(kr * 128 + q * 16));
        CP16(sB + so, Bb + (size_t)kr * NPAD + q * 8);
    }
}

__global__ __launch_bounds__(256, 2) void k_gemm() {
    extern __shared__ __align__(1024) char smem[];
    const uint32_t sb = smem_u32(smem);
    const int tid = threadIdx.x, lane = tid & 31, wid = tid >> 5;
    const int m0 = blockIdx.y * 128;
    const int n0 = blockIdx.x * 64;
    const int c0 = blockIdx.z * 11;
    const int nc = (blockIdx.z == 2) ? 10 : 11;
    const int warp_m = (wid & 3) * 32;
    const int warp_n = (wid >> 2) * 32;

    float acc[2][4][4] = {};

    gemm_issue(tid, m0, n0, c0, sb, 0); CP_COMMIT();

    for (int ci = 0; ci < nc; ++ci) {
        if (ci + 1 < nc) {
            gemm_issue(tid, m0, n0, c0 + ci + 1, sb, (ci + 1) & 1);
            CP_COMMIT();
            CP_WAIT1();
        } else {
            CP_WAIT0();
        }
        __syncthreads();

        const uint32_t sA = sb + (ci & 1) * 24576;
        const uint32_t sB = sA + 16384;
#pragma unroll
        for (int s = 0; s < 4; ++s) {
            uint32_t aH[2][4], bF[4][2];
            const int kh = s * 16 + (lane >> 4) * 8;
#pragma unroll
            for (int i = 0; i < 2; ++i) {
                int row = warp_m + i * 16 + ((lane >> 3) & 1) * 8 + (lane & 7);
                uint32_t so = SW128((uint32_t)(row * 128 + kh * 2));
                LDSM_X4(aH[i][0], aH[i][1], aH[i][2], aH[i][3], sA + so);
            }
            const int kr = s * 16 + ((lane >> 3) & 1) * 8 + (lane & 7);
#pragma unroll
            for (int j2 = 0; j2 < 2; ++j2) {
                int ncol = warp_n + j2 * 16 + (lane >> 4) * 8;
                uint32_t bd = sB + SW128((uint32_t)(kr * 128 + ncol * 2));
                LDSM_X4T(bF[j2 * 2][0], bF[j2 * 2][1],
                         bF[j2 * 2 + 1][0], bF[j2 * 2 + 1][1], bd);
            }
#pragma unroll
            for (int i = 0; i < 2; ++i)
#pragma unroll
                for (int j = 0; j < 4; ++j)
                    MMA16816F16(acc[i][j], aH[i], bF[j]);
        }
        __syncthreads();
    }

    float* dst = g_part + (size_t)blockIdx.z * PART2;
#pragma unroll
    for (int i = 0; i < 2; ++i)
#pragma unroll
        for (int j = 0; j < 4; ++j) {
            int r = m0 + warp_m + i * 16 + (lane >> 2);
            int cC = n0 + warp_n + j * 8 + (lane & 3) * 2;
            *(float2*)&dst[(size_t)r * NPAD + cC] = make_float2(acc[i][j][0], acc[i][j][1]);
            *(float2*)&dst[(size_t)(r + 8) * NPAD + cC] = make_float2(acc[i][j][2], acc[i][j][3]);
        }
}

// ============================================================================
// Tensor-core tail: 16 (b,n) rows per block (= 2 b), 512 thr (16 warps).
//  A: T1 = z_hi/lo @ W1zh (m16n8k16; frags built directly), + base + bias,
//     relu -> h stored hi/lo fp16 in smem (rows padded to 520 for banks)
//  B: G = h_hi/lo @ W2h, 4 k-slices x 4 n-chunks of warps, partials in smem
//  out[row] = sum_o (G[row,o]+bep2[o]+p[b,o]) * z[row,o]
// ============================================================================
#define ZSTR 36
#define HSTR 520

__global__ __launch_bounds__(512, 2) void k_tail(
    const float* __restrict__ z, const float* __restrict__ bep1,
    const float* __restrict__ bep2,
    const float* __restrict__ bp1, const float* __restrict__ Wp2,
    const float* __restrict__ bp2, const float* __restrict__ Wp3,
    const float* __restrict__ bp3, float* __restrict__ out)
{
    extern __shared__ float dsm[];
    float* zs     = dsm;                        // [16][ZSTR]
    float* base_s = dsm + 16 * ZSTR;            // [2][512]
    float* ps     = base_s + 1024;              // [64]
    float* gbuf   = ps + 64;                    // [4][16][32]
    __half* hs_hi = (__half*)(gbuf + 2048);     // [16][HSTR]
    __half* hs_lo = hs_hi + 16 * HSTR;          // [16][HSTR]

    const int t = threadIdx.x;
    const int lane = t & 31, w = t >> 5;
    const int gr = lane >> 2, c2 = (lane & 3) * 2;
    const int r0 = blockIdx.x * 16;
    const int b0 = blockIdx.x * 2;

    {   // z tile + base rows (coalesced)
        const int row = t >> 5, o = t & 31;
        zs[row * ZSTR + o] = z[(size_t)(r0 + row) * 32 + o];
        base_s[t]       = g_part[(size_t)b0 * NPAD + t]
                        + g_part[PART2 + (size_t)b0 * NPAD + t]
                        + g_part[2 * PART2 + (size_t)b0 * NPAD + t] + bep1[t];
        base_s[512 + t] = g_part[(size_t)(b0 + 1) * NPAD + t]
                        + g_part[PART2 + (size_t)(b0 + 1) * NPAD + t]
                        + g_part[2 * PART2 + (size_t)(b0 + 1) * NPAD + t] + bep1[t];
    }
    __syncthreads();

    // ---- phase A: T1[16,512] = z[16,32] @ W1z[32,512], warp w: n-slice w*32 ----
    {
        const int wn = w * 32;
        uint32_t aH[2][4], aL[2][4];
#pragma unroll
        for (int s = 0; s < 2; ++s)
#pragma unroll
            for (int hk = 0; hk < 2; ++hk)
#pragma unroll
                for (int rr = 0; rr < 2; ++rr) {
                    float2 v = *(float2*)&zs[(gr + rr * 8) * ZSTR + s * 16 + hk * 8 + c2];
                    __half h0 = __float2half(v.x), h1 = __float2half(v.y);
                    int ri = hk * 2 + rr;
                    aH[s][ri] = packh2(h0, h1);
                    aL[s][ri] = packh2(__float2half(v.x - __half2float(h0)),
                                       __float2half(v.y - __half2float(h1)));
                }
        uint32_t bw1[4][2][2];
#pragma unroll
        for (int nch = 0; nch < 4; ++nch)
#pragma unroll
            for (int s = 0; s < 2; ++s) {
                int n = wn + nch * 8 + gr;
                bw1[nch][s][0] = packh2(g_W1zh[(s * 16 + c2) * 512 + n],
                                        g_W1zh[(s * 16 + c2 + 1) * 512 + n]);
                bw1[nch][s][1] = packh2(g_W1zh[(s * 16 + c2 + 8) * 512 + n],
                                        g_W1zh[(s * 16 + c2 + 9) * 512 + n]);
            }
        float cfr[4][4] = {};
#pragma unroll
        for (int nch = 0; nch < 4; ++nch)
#pragma unroll
            for (int s = 0; s < 2; ++s) {
                MMA16816F16(cfr[nch], aH[s], bw1[nch][s]);
                MMA16816F16(cfr[nch], aL[s], bw1[nch][s]);
            }
#pragma unroll
        for (int nch = 0; nch < 4; ++nch) {
            int j = wn + nch * 8 + c2;
            float v00 = fmaxf(cfr[nch][0] + base_s[j], 0.f);
            float v01 = fmaxf(cfr[nch][1] + base_s[j + 1], 0.f);
            float v10 = fmaxf(cfr[nch][2] + base_s[512 + j], 0.f);
            float v11 = fmaxf(cfr[nch][3] + base_s[512 + j + 1], 0.f);
            __half a0 = __float2half(v00), a1 = __float2half(v01);
            __half b0h = __float2half(v10), b1h = __float2half(v11);
            *(uint32_t*)&hs_hi[gr * HSTR + j] = packh2(a0, a1);
            *(uint32_t*)&hs_lo[gr * HSTR + j] =
                packh2(__float2half(v00 - __half2float(a0)),
                       __float2half(v01 - __half2float(a1)));
            *(uint32_t*)&hs_hi[(gr + 8) * HSTR + j] = packh2(b0h, b1h);
            *(uint32_t*)&hs_lo[(gr + 8) * HSTR + j] =
                packh2(__float2half(v10 - __half2float(b0h)),
                       __float2half(v11 - __half2float(b1h)));
        }
    }
    __syncthreads();

    // ---- phase B: G[16,32] = h[16,512] @ W2[512,32]; warp = (kslice, nchunk) ----
    {
        const int ks = w >> 2, nch = w & 3;
        uint32_t bw2[8][2];
#pragma unroll
        for (int kst = 0; kst < 8; ++kst) {
            int k = ks * 128 + kst * 16;
            int n = nch * 8 + gr;
            bw2[kst][0] = packh2(g_W2h[(k + c2) * 32 + n], g_W2h[(k + c2 + 1) * 32 + n]);
            bw2[kst][1] = packh2(g_W2h[(k + c2 + 8) * 32 + n], g_W2h[(k + c2 + 9) * 32 + n]);
        }
        float gfr[4] = {};
#pragma unroll
        for (int kst = 0; kst < 8; ++kst) {
            int k = ks * 128 + kst * 16;
            uint32_t aH2[4], aL2[4];
            aH2[0] = *(uint32_t*)&hs_hi[gr * HSTR + k + c2];
            aH2[1] = *(uint32_t*)&hs_hi[(gr + 8) * HSTR + k + c2];
            aH2[2] = *(uint32_t*)&hs_hi[gr * HSTR + k + c2 + 8];
            aH2[3] = *(uint32_t*)&hs_hi[(gr + 8) * HSTR + k + c2 + 8];
            aL2[0] = *(uint32_t*)&hs_lo[gr * HSTR + k + c2];
            aL2[1] = *(uint32_t*)&hs_lo[(gr + 8) * HSTR + k + c2];
            aL2[2] = *(uint32_t*)&hs_lo[gr * HSTR + k + c2 + 8];
            aL2[3] = *(uint32_t*)&hs_lo[(gr + 8) * HSTR + k + c2 + 8];
            MMA16816F16(gfr, aH2, bw2[kst]);
            MMA16816F16(gfr, aL2, bw2[kst]);
        }
        int o = nch * 8 + c2;
        *(float2*)&gbuf[(ks * 16 + gr) * 32 + o] = make_float2(gfr[0], gfr[1]);
        *(float2*)&gbuf[(ks * 16 + gr + 8) * 32 + o] = make_float2(gfr[2], gfr[3]);
    }

    // prior ensemble layers 2-3 (64 threads; g_part L2-warm)
    if (t < 64) {
        const int bb = b0 + (t >> 5), e = t & 31;
        const size_t off = (size_t)bb * NPAD + 512 + e * 5;
        float s1[5];
#pragma unroll
        for (int k = 0; k < 5; ++k)
            s1[k] = fmaxf(g_part[off + k] + g_part[PART2 + off + k]
                          + g_part[2 * PART2 + off + k] + bp1[e * 5 + k], 0.f);
        float p = bp3[e];
#pragma unroll
        for (int g = 0; g < 5; ++g) {
            float s = bp2[e * 5 + g];
#pragma unroll
            for (int k = 0; k < 5; ++k) s += s1[k] * Wp2[e * 25 + k * 5 + g];
            p += fmaxf(s, 0.f) * Wp3[e * 5 + g];
        }
        ps[t] = p;
    }
    __syncthreads();

    // ---- final: out[row] = sum_o (G+bep2+p)*z ; warp w = row, lane = o ----
    {
        const int row = w, o = lane;
        float g = gbuf[row * 32 + o] + gbuf[512 + row * 32 + o]
                + gbuf[1024 + row * 32 + o] + gbuf[1536 + row * 32 + o];
        float val = (g + bep2[o] + ps[(row >> 3) * 32 + o]) * zs[row * ZSTR + o];
#pragma unroll
        for (int off = 16; off > 0; off >>= 1)
            val += __shfl_xor_sync(0xffffffffu, val, off);
        if (o == 0) out[r0 + row] = val;
    }
}

// ============================================================================
extern "C" void kernel_launch(void* const* d_in, const int* in_sizes, int n_in,
                              void* d_out, int out_size)
{
    const float* x    = (const float*)d_in[0];
    const float* feat = (const float*)d_in[1];
    const float* z    = (const float*)d_in[2];
    const float* Wep1 = (const float*)d_in[3];
    const float* bep1 = (const float*)d_in[4];
    const float* Wep2 = (const float*)d_in[5];
    const float* bep2 = (const float*)d_in[6];
    const float* Wp1  = (const float*)d_in[7];
    const float* bp1  = (const float*)d_in[8];
    const float* Wp2  = (const float*)d_in[9];
    const float* bp2  = (const float*)d_in[10];
    const float* Wp3  = (const float*)d_in[11];
    const float* bp3  = (const float*)d_in[12];
    float* out = (float*)d_out;

    const int tail_smem = (16 * ZSTR + 1024 + 64 + 2048) * 4 + 2 * 16 * HSTR * 2;

    static int smem_set = 0;
    if (!smem_set) {
        cudaFuncSetAttribute(k_gemm, cudaFuncAttributeMaxDynamicSharedMemorySize, 49152);
        cudaFuncSetAttribute(k_tail, cudaFuncAttributeMaxDynamicSharedMemorySize, 50000);
        smem_set = 1;
    }

    k_front<<<A_BLOCKS + W_BLOCKS + FH_BLOCKS, 256>>>(x, feat, Wep1, Wp1, Wep2);
    k_gemm<<<dim3(11, 16, 3), 256, 49152>>>();
    k_tail<<<1024, 512, tail_smem>>>(z, bep1, bep2, bp1, Wp2, bp2, Wp3, bp3, out);
}

// round 15
// speedup vs baseline: 2.0106x; 1.1314x over previous
#include <cuda_runtime.h>
#include <cuda_fp16.h>
#include <cstdint>

typedef unsigned long long ULL;

#define NPAD 704
#define PART2 (2048L * NPAD)

// ---------------- scratch (static device arrays; no runtime alloc) ----------
__device__ __half g_Ah[2048L * 2048];          // fp16 of concat(x,feature)  8MB
__device__ __half g_Bh[2048L * NPAD];          // fp16 [Wep1^T | Wp1 fold | 0]
__device__ float g_part[3 * PART2];            // K-split partial outputs
__device__ uint32_t g_W1zf[512 * 16];          // frag-ordered W1z (per warp/lane)
__device__ uint32_t g_W2f[512 * 16];           // frag-ordered Wep2

// ---------------- helpers ----------------------------------------------------
__device__ __forceinline__ uint32_t smem_u32(const void* p) {
    uint32_t a;
    asm("{ .reg .u64 t; cvta.to.shared.u64 t, %1; cvt.u32.u64 %0, t; }" : "=r"(a) : "l"(p));
    return a;
}
__device__ __forceinline__ uint32_t packh2(__half a, __half b) {
    __half2 p = __halves2half2(a, b);
    return *(uint32_t*)&p;
}
#define SW128(o) ((o) ^ (((o) >> 3) & 0x70))

#define LDSM_X4(r0, r1, r2, r3, addr) \
    asm volatile("ldmatrix.sync.aligned.m8n8.x4.shared.b16 {%0,%1,%2,%3}, [%4];" \
                 : "=r"(r0), "=r"(r1), "=r"(r2), "=r"(r3) : "r"(addr))
#define LDSM_X4T(r0, r1, r2, r3, addr) \
    asm volatile("ldmatrix.sync.aligned.m8n8.x4.trans.shared.b16 {%0,%1,%2,%3}, [%4];" \
                 : "=r"(r0), "=r"(r1), "=r"(r2), "=r"(r3) : "r"(addr))
#define MMA16816F16(d, a, b) \
    asm volatile("mma.sync.aligned.m16n8k16.row.col.f32.f16.f16.f32 " \
                 "{%0,%1,%2,%3}, {%4,%5,%6,%7}, {%8,%9}, {%0,%1,%2,%3};" \
                 : "+f"((d)[0]), "+f"((d)[1]), "+f"((d)[2]), "+f"((d)[3]) \
                 : "r"((a)[0]), "r"((a)[1]), "r"((a)[2]), "r"((a)[3]), \
                   "r"((b)[0]), "r"((b)[1]))
#define CP16(dst, src) \
    asm volatile("cp.async.cg.shared.global [%0], [%1], 16;" :: "r"(dst), "l"(src))
#define CP_COMMIT() asm volatile("cp.async.commit_group;" ::: "memory")
#define CP_WAIT1()  asm volatile("cp.async.wait_group 1;" ::: "memory")
#define CP_WAIT0()  asm volatile("cp.async.wait_group 0;" ::: "memory")

// ============================================================================
// Front kernel: dispatcher [convert_A | convert_W | weight frag bake]
// ============================================================================
#define A_BLOCKS  2048
#define W_BLOCKS  704
#define FH_BLOCKS 64

__global__ __launch_bounds__(256) void k_front(
    const float* __restrict__ x, const float* __restrict__ f,
    const float* __restrict__ Wep1, const float* __restrict__ Wp1,
    const float* __restrict__ W2)
{
    const int t = threadIdx.x;
    const int bid = blockIdx.x;

    if (bid < A_BLOCKS) {
        // ---- convert A: single fp16 plane, source read once ----
        int idx = bid * 256 + t;                 // over 2048*256
        int m = idx >> 8;
        int k = (idx & 255) * 8;
        const float* src = (k < 1024) ? (x + (size_t)m * 1024 + k)
                                      : (f + (size_t)m * 1024 + (k - 1024));
        float4 f0 = *(const float4*)src;
        float4 f1 = *(const float4*)(src + 4);
        float vv[8] = {f0.x, f0.y, f0.z, f0.w, f1.x, f1.y, f1.z, f1.w};
        union { __half h[8]; uint4 u; } H;
#pragma unroll
        for (int e = 0; e < 8; ++e) H.h[e] = __float2half(vv[e]);
        *(uint4*)(g_Ah + (size_t)m * 2048 + k) = H.u;
    } else if (bid < A_BLOCKS + W_BLOCKS) {
        // ---- convert W: [2048 k][704 n] fp16; 0-511 Wep1, 512-671 Wp1, pad 0 ----
        int idx = (bid - A_BLOCKS) * 256 + t;    // over 2048*88
        int k = idx / 88;
        int n = (idx - k * 88) * 8;
        float vv[8];
        if (n < 512) {
            float4 w0 = *(const float4*)&Wep1[(size_t)k * 512 + n];
            float4 w1 = *(const float4*)&Wep1[(size_t)k * 512 + n + 4];
            vv[0] = w0.x; vv[1] = w0.y; vv[2] = w0.z; vv[3] = w0.w;
            vv[4] = w1.x; vv[5] = w1.y; vv[6] = w1.z; vv[7] = w1.w;
        } else if (n < 672) {
#pragma unroll
            for (int e = 0; e < 8; ++e) {
                int u = n + e - 512, en = u / 5, r = u - en * 5;
                vv[e] = (k < 1024) ? Wp1[en * 5120 + k * 5 + r] : 0.f;
            }
        } else {
#pragma unroll
            for (int e = 0; e < 8; ++e) vv[e] = 0.f;
        }
        union { __half h[8]; uint4 u; } O;
#pragma unroll
        for (int e = 0; e < 8; ++e) O.h[e] = __float2half(vv[e]);
        *(uint4*)(g_Bh + (size_t)k * NPAD + n) = O.u;
    } else {
        // ---- bake weight fragments: one uint32 per thread, frag-ordered ----
        int gid = (bid - A_BLOCKS - W_BLOCKS) * 256 + t;   // over 16384
        int e = gid & 8191;
        int idx = e & 15;            // position in the thread's 16-reg frag set
        int wl = e >> 4;             // 0..511 = warp*32 + lane
        int w = wl >> 5, l = wl & 31;
        int gr = l >> 2, c2 = (l & 3) * 2;
        if (gid < 8192) {
            // bw1[nch][s][r]: idx = nch*4 + s*2 + r
            int nch = idx >> 2, s = (idx >> 1) & 1, r = idx & 1;
            int n = w * 32 + nch * 8 + gr;
            int row = s * 16 + c2 + r * 8;
            const float* W1z = Wep1 + 2048 * 512;
            g_W1zf[wl * 16 + idx] = packh2(__float2half(W1z[row * 512 + n]),
                                           __float2half(W1z[(row + 1) * 512 + n]));
        } else {
            // bw2[kst][r]: idx = kst*2 + r; warp w -> ks=w>>2, nch=w&3
            int kst = idx >> 1, r = idx & 1;
            int k = (w >> 2) * 128 + kst * 16 + c2 + r * 8;
            int n = (w & 3) * 8 + gr;
            g_W2f[wl * 16 + idx] = packh2(__float2half(W2[k * 32 + n]),
                                          __float2half(W2[(k + 1) * 32 + n]));
        }
    }
}

// ============================================================================
// HMMA GEMM (fp16 single-product): D[2048,704] = A[2048,2048] @ B[2048,704].
// BM=128 BN=64 BK=64, 256 thr (8 warps, 32x32 warp tiles), 2-stage cp.async.
// ============================================================================
__device__ __forceinline__ void gemm_issue(int tid, int m0, int n0, int chunk,
                                           uint32_t sb, int stage) {
    const __half* Ah = g_Ah + (size_t)m0 * 2048 + chunk * 64;
    const __half* Bb = g_Bh + (size_t)chunk * 64 * NPAD + n0;
    uint32_t sA = sb + stage * 24576;
    uint32_t sB = sA + 16384;
#pragma unroll
    for (int i = 0; i < 4; ++i) {
        int v = tid * 4 + i, m = v >> 3, q = v & 7;
        uint32_t so = SW128((uint32_t)(m * 128 + q * 16));
        CP16(sA + so, Ah + (size_t)m * 2048 + q * 8);
    }
#pragma unroll
    for (int i = 0; i < 2; ++i) {
        int v = tid * 2 + i, kr = v >> 3, q = v & 7;
        uint32_t so = SW128((uint32_t)(kr * 128 + q * 16));
        CP16(sB + so, Bb + (size_t)kr * NPAD + q * 8);
    }
}

__global__ __launch_bounds__(256, 2) void k_gemm() {
    extern __shared__ __align__(1024) char smem[];
    const uint32_t sb = smem_u32(smem);
    const int tid = threadIdx.x, lane = tid & 31, wid = tid >> 5;
    const int m0 = blockIdx.y * 128;
    const int n0 = blockIdx.x * 64;
    const int c0 = blockIdx.z * 11;
    const int nc = (blockIdx.z == 2) ? 10 : 11;
    const int warp_m = (wid & 3) * 32;
    const int warp_n = (wid >> 2) * 32;

    float acc[2][4][4] = {};

    gemm_issue(tid, m0, n0, c0, sb, 0); CP_COMMIT();

    for (int ci = 0; ci < nc; ++ci) {
        if (ci + 1 < nc) {
            gemm_issue(tid, m0, n0, c0 + ci + 1, sb, (ci + 1) & 1);
            CP_COMMIT();
            CP_WAIT1();
        } else {
            CP_WAIT0();
        }
        __syncthreads();

        const uint32_t sA = sb + (ci & 1) * 24576;
        const uint32_t sB = sA + 16384;
#pragma unroll
        for (int s = 0; s < 4; ++s) {
            uint32_t aH[2][4], bF[4][2];
            const int kh = s * 16 + (lane >> 4) * 8;
#pragma unroll
            for (int i = 0; i < 2; ++i) {
                int row = warp_m + i * 16 + ((lane >> 3) & 1) * 8 + (lane & 7);
                uint32_t so = SW128((uint32_t)(row * 128 + kh * 2));
                LDSM_X4(aH[i][0], aH[i][1], aH[i][2], aH[i][3], sA + so);
            }
            const int kr = s * 16 + ((lane >> 3) & 1) * 8 + (lane & 7);
#pragma unroll
            for (int j2 = 0; j2 < 2; ++j2) {
                int ncol = warp_n + j2 * 16 + (lane >> 4) * 8;
                uint32_t bd = sB + SW128((uint32_t)(kr * 128 + ncol * 2));
                LDSM_X4T(bF[j2 * 2][0], bF[j2 * 2][1],
                         bF[j2 * 2 + 1][0], bF[j2 * 2 + 1][1], bd);
            }
#pragma unroll
            for (int i = 0; i < 2; ++i)
#pragma unroll
                for (int j = 0; j < 4; ++j)
                    MMA16816F16(acc[i][j], aH[i], bF[j]);
        }
        __syncthreads();
    }

    float* dst = g_part + (size_t)blockIdx.z * PART2;
#pragma unroll
    for (int i = 0; i < 2; ++i)
#pragma unroll
        for (int j = 0; j < 4; ++j) {
            int r = m0 + warp_m + i * 16 + (lane >> 2);
            int cC = n0 + warp_n + j * 8 + (lane & 3) * 2;
            *(float2*)&dst[(size_t)r * NPAD + cC] = make_float2(acc[i][j][0], acc[i][j][1]);
            *(float2*)&dst[(size_t)(r + 8) * NPAD + cC] = make_float2(acc[i][j][2], acc[i][j][3]);
        }
}

// ============================================================================
// Tensor-core tail: 16 (b,n) rows per block (= 2 b), 512 thr (16 warps).
// Weight frags loaded pre-baked (4x LDG.128 per thread per phase).
// ============================================================================
#define ZSTR 36
#define HSTR 520

__global__ __launch_bounds__(512, 2) void k_tail(
    const float* __restrict__ z, const float* __restrict__ bep1,
    const float* __restrict__ bep2,
    const float* __restrict__ bp1, const float* __restrict__ Wp2,
    const float* __restrict__ bp2, const float* __restrict__ Wp3,
    const float* __restrict__ bp3, float* __restrict__ out)
{
    extern __shared__ float dsm[];
    float* zs     = dsm;                        // [16][ZSTR]
    float* base_s = dsm + 16 * ZSTR;            // [2][512]
    float* ps     = base_s + 1024;              // [64]
    float* gbuf   = ps + 64;                    // [4][16][32]
    __half* hs_hi = (__half*)(gbuf + 2048);     // [16][HSTR]
    __half* hs_lo = hs_hi + 16 * HSTR;          // [16][HSTR]

    const int t = threadIdx.x;
    const int lane = t & 31, w = t >> 5;
    const int gr = lane >> 2, c2 = (lane & 3) * 2;
    const int r0 = blockIdx.x * 16;
    const int b0 = blockIdx.x * 2;

    // pre-baked weight frags: 4+4 LDG.128 per thread
    uint32_t bw1[16], bw2[16];
    {
        const uint4* p1 = (const uint4*)(g_W1zf + t * 16);
        const uint4* p2 = (const uint4*)(g_W2f + t * 16);
#pragma unroll
        for (int q = 0; q < 4; ++q) {
            *(uint4*)&bw1[q * 4] = p1[q];
            *(uint4*)&bw2[q * 4] = p2[q];
        }
    }

    {   // z tile + base rows (coalesced)
        const int row = t >> 5, o = t & 31;
        zs[row * ZSTR + o] = z[(size_t)(r0 + row) * 32 + o];
        base_s[t]       = g_part[(size_t)b0 * NPAD + t]
                        + g_part[PART2 + (size_t)b0 * NPAD + t]
                        + g_part[2 * PART2 + (size_t)b0 * NPAD + t] + bep1[t];
        base_s[512 + t] = g_part[(size_t)(b0 + 1) * NPAD + t]
                        + g_part[PART2 + (size_t)(b0 + 1) * NPAD + t]
                        + g_part[2 * PART2 + (size_t)(b0 + 1) * NPAD + t] + bep1[t];
    }
    __syncthreads();

    // ---- phase A: T1[16,512] = z[16,32] @ W1z[32,512], warp w: n-slice w*32 ----
    {
        const int wn = w * 32;
        uint32_t aH[2][4], aL[2][4];
#pragma unroll
        for (int s = 0; s < 2; ++s)
#pragma unroll
            for (int hk = 0; hk < 2; ++hk)
#pragma unroll
                for (int rr = 0; rr < 2; ++rr) {
                    float2 v = *(float2*)&zs[(gr + rr * 8) * ZSTR + s * 16 + hk * 8 + c2];
                    __half h0 = __float2half(v.x), h1 = __float2half(v.y);
                    int ri = hk * 2 + rr;
                    aH[s][ri] = packh2(h0, h1);
                    aL[s][ri] = packh2(__float2half(v.x - __half2float(h0)),
                                       __float2half(v.y - __half2float(h1)));
                }
        float cfr[4][4] = {};
#pragma unroll
        for (int nch = 0; nch < 4; ++nch)
#pragma unroll
            for (int s = 0; s < 2; ++s) {
                uint32_t* bb = &bw1[nch * 4 + s * 2];
                MMA16816F16(cfr[nch], aH[s], bb);
                MMA16816F16(cfr[nch], aL[s], bb);
            }
#pragma unroll
        for (int nch = 0; nch < 4; ++nch) {
            int j = wn + nch * 8 + c2;
            float v00 = fmaxf(cfr[nch][0] + base_s[j], 0.f);
            float v01 = fmaxf(cfr[nch][1] + base_s[j + 1], 0.f);
            float v10 = fmaxf(cfr[nch][2] + base_s[512 + j], 0.f);
            float v11 = fmaxf(cfr[nch][3] + base_s[512 + j + 1], 0.f);
            __half a0 = __float2half(v00), a1 = __float2half(v01);
            __half b0h = __float2half(v10), b1h = __float2half(v11);
            *(uint32_t*)&hs_hi[gr * HSTR + j] = packh2(a0, a1);
            *(uint32_t*)&hs_lo[gr * HSTR + j] =
                packh2(__float2half(v00 - __half2float(a0)),
                       __float2half(v01 - __half2float(a1)));
            *(uint32_t*)&hs_hi[(gr + 8) * HSTR + j] = packh2(b0h, b1h);
            *(uint32_t*)&hs_lo[(gr + 8) * HSTR + j] =
                packh2(__float2half(v10 - __half2float(b0h)),
                       __float2half(v11 - __half2float(b1h)));
        }
    }
    __syncthreads();

    // ---- phase B: G[16,32] = h[16,512] @ W2[512,32]; warp = (kslice, nchunk) ----
    {
        const int ks = w >> 2, nch = w & 3;
        float gfr[4] = {};
#pragma unroll
        for (int kst = 0; kst < 8; ++kst) {
            int k = ks * 128 + kst * 16;
            uint32_t aH2[4], aL2[4];
            aH2[0] = *(uint32_t*)&hs_hi[gr * HSTR + k + c2];
            aH2[1] = *(uint32_t*)&hs_hi[(gr + 8) * HSTR + k + c2];
            aH2[2] = *(uint32_t*)&hs_hi[gr * HSTR + k + c2 + 8];
            aH2[3] = *(uint32_t*)&hs_hi[(gr + 8) * HSTR + k + c2 + 8];
            aL2[0] = *(uint32_t*)&hs_lo[gr * HSTR + k + c2];
            aL2[1] = *(uint32_t*)&hs_lo[(gr + 8) * HSTR + k + c2];
            aL2[2] = *(uint32_t*)&hs_lo[gr * HSTR + k + c2 + 8];
            aL2[3] = *(uint32_t*)&hs_lo[(gr + 8) * HSTR + k + c2 + 8];
            uint32_t* bb = &bw2[kst * 2];
            MMA16816F16(gfr, aH2, bb);
            MMA16816F16(gfr, aL2, bb);
        }
        int o = nch * 8 + c2;
        *(float2*)&gbuf[(ks * 16 + gr) * 32 + o] = make_float2(gfr[0], gfr[1]);
        *(float2*)&gbuf[(ks * 16 + gr + 8) * 32 + o] = make_float2(gfr[2], gfr[3]);
    }

    // prior ensemble layers 2-3 (64 threads; g_part L2-warm)
    if (t < 64) {
        const int bb = b0 + (t >> 5), e = t & 31;
        const size_t off = (size_t)bb * NPAD + 512 + e * 5;
        float s1[5];
#pragma unroll
        for (int k = 0; k < 5; ++k)
            s1[k] = fmaxf(g_part[off + k] + g_part[PART2 + off + k]
                          + g_part[2 * PART2 + off + k] + bp1[e * 5 + k], 0.f);
        float p = bp3[e];
#pragma unroll
        for (int g = 0; g < 5; ++g) {
            float s = bp2[e * 5 + g];
#pragma unroll
            for (int k = 0; k < 5; ++k) s += s1[k] * Wp2[e * 25 + k * 5 + g];
            p += fmaxf(s, 0.f) * Wp3[e * 5 + g];
        }
        ps[t] = p;
    }
    __syncthreads();

    // ---- final: out[row] = sum_o (G+bep2+p)*z ; warp w = row, lane = o ----
    {
        const int row = w, o = lane;
        float g = gbuf[row * 32 + o] + gbuf[512 + row * 32 + o]
                + gbuf[1024 + row * 32 + o] + gbuf[1536 + row * 32 + o];
        float val = (g + bep2[o] + ps[(row >> 3) * 32 + o]) * zs[row * ZSTR + o];
#pragma unroll
        for (int off = 16; off > 0; off >>= 1)
            val += __shfl_xor_sync(0xffffffffu, val, off);
        if (o == 0) out[r0 + row] = val;
    }
}

// ============================================================================
extern "C" void kernel_launch(void* const* d_in, const int* in_sizes, int n_in,
                              void* d_out, int out_size)
{
    const float* x    = (const float*)d_in[0];
    const float* feat = (const float*)d_in[1];
    const float* z    = (const float*)d_in[2];
    const float* Wep1 = (const float*)d_in[3];
    const float* bep1 = (const float*)d_in[4];
    const float* Wep2 = (const float*)d_in[5];
    const float* bep2 = (const float*)d_in[6];
    const float* Wp1  = (const float*)d_in[7];
    const float* bp1  = (const float*)d_in[8];
    const float* Wp2  = (const float*)d_in[9];
    const float* bp2  = (const float*)d_in[10];
    const float* Wp3  = (const float*)d_in[11];
    const float* bp3  = (const float*)d_in[12];
    float* out = (float*)d_out;

    const int tail_smem = (16 * ZSTR + 1024 + 64 + 2048) * 4 + 2 * 16 * HSTR * 2;

    static int smem_set = 0;
    if (!smem_set) {
        cudaFuncSetAttribute(k_gemm, cudaFuncAttributeMaxDynamicSharedMemorySize, 49152);
        cudaFuncSetAttribute(k_tail, cudaFuncAttributeMaxDynamicSharedMemorySize, 50000);
        smem_set = 1;
    }

    k_front<<<A_BLOCKS + W_BLOCKS + FH_BLOCKS, 256>>>(x, feat, Wep1, Wp1, Wep2);
    k_gemm<<<dim3(11, 16, 3), 256, 49152>>>();
    k_tail<<<1024, 512, tail_smem>>>(z, bep1, bep2, bp1, Wp2, bp2, Wp3, bp3, out);
}